// round 6
// baseline (speedup 1.0000x reference)
#include <cuda_runtime.h>
#include <cstdint>

#define N_NODES 65536
#define N_EDGES 1048576
#define EMB 64
#define IN_DIM 128
#define OUT_DIM 32
#define N_HIDDEN 4
#define N_CHUNKS 1024   // 65536 / 64

// ---------------- scratch (static device globals; no allocation) ----------------
__device__ float g_h[N_NODES * EMB];        // layer activations
__device__ float g_hw[N_NODES * EMB];       // post-GEMM, pre-aggregation
__device__ float g_dinv[N_NODES];           // 1/sqrt(deg)
__device__ float g_deg[N_NODES];            // weighted in-degree (atomic float)
__device__ int   g_count[N_NODES];          // in-degree histogram
__device__ int   g_rowptr[N_NODES + 1];     // CSR row pointers (by dst)
__device__ int   g_work[N_NODES];           // fill cursors (copy of rowptr)
__device__ int2  g_csr[N_EDGES];            // CSR: {src, float_bits(norm_w)}
__device__ int   g_choff[N_CHUNKS];         // exclusive chunk offsets
__device__ int   g_part[N_CHUNKS];          // chunk partial sums
__device__ int   g_is64;                    // edge_index dtype flag

// ---------------- dtype detection ----------------
__global__ void detect_kernel(const unsigned int* __restrict__ w) {
    __shared__ int s_any;
    if (threadIdx.x == 0) s_any = 0;
    __syncthreads();
    unsigned int v = w[2 * threadIdx.x + 1];
    if (v != 0) s_any = 1;
    __syncthreads();
    if (threadIdx.x == 0) g_is64 = (s_any == 0) ? 1 : 0;
}

__device__ __forceinline__ int load_idx(const void* p, int i) {
    if (g_is64) return (int)((const long long*)p)[i];
    return ((const int*)p)[i];
}

// ---------------- pass 1: count + weighted degree ----------------
__global__ void count_deg_kernel(const void* __restrict__ eidx,
                                 const float* __restrict__ ew) {
    int e = blockIdx.x * blockDim.x + threadIdx.x;
    if (e >= N_EDGES) return;
    int dst = load_idx(eidx, N_EDGES + e);
    atomicAdd(&g_count[dst], 1);
    atomicAdd(&g_deg[dst], ew[e]);
}

// ---------------- scan phase 1 ----------------
__global__ void chunk_reduce_kernel() {
    int warp = (blockIdx.x * blockDim.x + threadIdx.x) >> 5;
    int lane = threadIdx.x & 31;
    if (warp >= N_CHUNKS) return;
    int base = warp * 64;
    int v = g_count[base + lane] + g_count[base + 32 + lane];
#pragma unroll
    for (int off = 16; off > 0; off >>= 1)
        v += __shfl_down_sync(0xffffffffu, v, off);
    if (lane == 0) g_part[warp] = v;
}

// ---------------- scan phase 2 ----------------
__global__ void scan_part_kernel() {
    __shared__ int s[N_CHUNKS];
    int t = threadIdx.x;
    int orig = g_part[t];
    s[t] = orig;
    __syncthreads();
    for (int off = 1; off < N_CHUNKS; off <<= 1) {
        int v = (t >= off) ? s[t - off] : 0;
        __syncthreads();
        s[t] += v;
        __syncthreads();
    }
    g_choff[t] = s[t] - orig;  // exclusive
}

// ---------------- scan phase 3: rowptr + work + dinv ----------------
__global__ void rowptr_dinv_kernel() {
    int warp = (blockIdx.x * blockDim.x + threadIdx.x) >> 5;
    int lane = threadIdx.x & 31;
    if (warp >= N_CHUNKS) return;
    int base = warp * 64;
    int c0 = g_count[base + lane];
    int c1 = g_count[base + 32 + lane];
    int i0 = c0, i1 = c1;
#pragma unroll
    for (int off = 1; off < 32; off <<= 1) {
        int v0 = __shfl_up_sync(0xffffffffu, i0, off);
        int v1 = __shfl_up_sync(0xffffffffu, i1, off);
        if (lane >= off) { i0 += v0; i1 += v1; }
    }
    int tot0 = __shfl_sync(0xffffffffu, i0, 31);
    int off = g_choff[warp];
    int r0 = off + i0 - c0;
    int r1 = off + tot0 + i1 - c1;
    g_rowptr[base + lane] = r0;
    g_rowptr[base + 32 + lane] = r1;
    g_work[base + lane] = r0;
    g_work[base + 32 + lane] = r1;
    if (warp == N_CHUNKS - 1 && lane == 31) g_rowptr[N_NODES] = N_EDGES;
    float d, r;
    d = 1.0f + g_deg[base + lane];
    r = rsqrtf(d);
    g_dinv[base + lane] = r * (1.5f - 0.5f * d * r * r);
    d = 1.0f + g_deg[base + 32 + lane];
    r = rsqrtf(d);
    g_dinv[base + 32 + lane] = r * (1.5f - 0.5f * d * r * r);
}

// ---------------- pass 3: fill CSR with normalized weights ----------------
__global__ void fill_kernel(const void* __restrict__ eidx,
                            const float* __restrict__ ew) {
    int e = blockIdx.x * blockDim.x + threadIdx.x;
    if (e >= N_EDGES) return;
    int src = load_idx(eidx, e);
    int dst = load_idx(eidx, N_EDGES + e);
    float w = ew[e] * g_dinv[src] * g_dinv[dst];
    int pos = atomicAdd(&g_work[dst], 1);
    g_csr[pos] = make_int2(src, __float_as_int(w));
}

// ---------------- GEMM: C[N,64] = A[N,K] @ W[K,64] ----------------
template <int K>
__global__ __launch_bounds__(256) void gemm_n64_kernel(
    const float* __restrict__ A, const float* __restrict__ W,
    float* __restrict__ C) {
    __shared__ float sw[K * 64];
    int tid = threadIdx.x, lane = tid & 31, warp = tid >> 5;
    for (int i = tid; i < K * 64; i += 256) sw[i] = W[i];
    __syncthreads();
    int row = blockIdx.x * 64 + warp * 8;
    for (int rr = 0; rr < 8; rr++, row++) {
        const float* a = A + (size_t)row * K;
        float ar[K / 32];
#pragma unroll
        for (int j = 0; j < K / 32; j++) ar[j] = a[lane + 32 * j];
        float acc0 = 0.f, acc1 = 0.f;
#pragma unroll
        for (int k = 0; k < K; k++) {
            float av = __shfl_sync(0xffffffffu, ar[k >> 5], k & 31);
            acc0 = fmaf(av, sw[k * 64 + lane], acc0);
            acc1 = fmaf(av, sw[k * 64 + lane + 32], acc1);
        }
        float* c = C + (size_t)row * 64;
        c[lane] = acc0;
        c[lane + 32] = acc1;
    }
}

// ---------------- aggregation + bias + ELU ----------------
// Warp per node. Metadata for up to 32 edges prefetched with ONE coalesced
// LDG.64 per batch, then distributed by shfl -> gather addresses are
// register-resident. Gathers issued in unrolled groups of 4 per half-warp
// (8 edges/body) so ptxas front-batches them (MLP>=4).
__global__ __launch_bounds__(256) void agg_elu_kernel(
    const float* __restrict__ hw, const float* __restrict__ bias) {
    int node = (blockIdx.x * blockDim.x + threadIdx.x) >> 5;
    int lane = threadIdx.x & 31;
    if (node >= N_NODES) return;
    int half = lane >> 4;     // 0 or 1
    int l16 = lane & 15;
    const float4* hw4 = (const float4*)hw;  // row = 16 float4
    float4 acc = make_float4(0.f, 0.f, 0.f, 0.f);
    if (half == 0) {
        float di = g_dinv[node];
        float ws = di * di;
        float4 r = hw4[(size_t)node * 16 + l16];
        acc.x = ws * r.x; acc.y = ws * r.y; acc.z = ws * r.z; acc.w = ws * r.w;
    }
    int s0 = g_rowptr[node], s1 = g_rowptr[node + 1];
    for (int b = s0; b < s1; b += 32) {
        // batch metadata prefetch: lane -> edge b+lane (coalesced)
        int2 meta = make_int2(0, 0);  // pad: src=0, w=0
        if (b + lane < s1) meta = g_csr[b + lane];
        int cnt = min(32, s1 - b);
        int j = 0;
        // unrolled: 8 edges per body, 4 gathers per half-warp
        for (; j + 8 <= cnt; j += 8) {
            int s_[4]; float w_[4];
#pragma unroll
            for (int u = 0; u < 4; u++) {
                int jj = j + 2 * u + half;
                s_[u] = __shfl_sync(0xffffffffu, meta.x, jj);
                w_[u] = __int_as_float(__shfl_sync(0xffffffffu, meta.y, jj));
            }
            float4 r0 = hw4[(size_t)s_[0] * 16 + l16];
            float4 r1 = hw4[(size_t)s_[1] * 16 + l16];
            float4 r2 = hw4[(size_t)s_[2] * 16 + l16];
            float4 r3 = hw4[(size_t)s_[3] * 16 + l16];
            acc.x = fmaf(w_[0], r0.x, acc.x); acc.y = fmaf(w_[0], r0.y, acc.y);
            acc.z = fmaf(w_[0], r0.z, acc.z); acc.w = fmaf(w_[0], r0.w, acc.w);
            acc.x = fmaf(w_[1], r1.x, acc.x); acc.y = fmaf(w_[1], r1.y, acc.y);
            acc.z = fmaf(w_[1], r1.z, acc.z); acc.w = fmaf(w_[1], r1.w, acc.w);
            acc.x = fmaf(w_[2], r2.x, acc.x); acc.y = fmaf(w_[2], r2.y, acc.y);
            acc.z = fmaf(w_[2], r2.z, acc.z); acc.w = fmaf(w_[2], r2.w, acc.w);
            acc.x = fmaf(w_[3], r3.x, acc.x); acc.y = fmaf(w_[3], r3.y, acc.y);
            acc.z = fmaf(w_[3], r3.z, acc.z); acc.w = fmaf(w_[3], r3.w, acc.w);
        }
        // tail: 2 edges per iter; jj <= cnt <= 31, pad lanes carry w=0, src=0
        for (; j < cnt; j += 2) {
            int jj = j + half;
            int s = __shfl_sync(0xffffffffu, meta.x, jj);
            float w = __int_as_float(__shfl_sync(0xffffffffu, meta.y, jj));
            float4 r = hw4[(size_t)s * 16 + l16];
            acc.x = fmaf(w, r.x, acc.x);
            acc.y = fmaf(w, r.y, acc.y);
            acc.z = fmaf(w, r.z, acc.z);
            acc.w = fmaf(w, r.w, acc.w);
        }
    }
    // fold half 1 into half 0
    acc.x += __shfl_down_sync(0xffffffffu, acc.x, 16);
    acc.y += __shfl_down_sync(0xffffffffu, acc.y, 16);
    acc.z += __shfl_down_sync(0xffffffffu, acc.z, 16);
    acc.w += __shfl_down_sync(0xffffffffu, acc.w, 16);
    if (half == 0) {
        float4 bb = ((const float4*)bias)[l16];
        acc.x += bb.x; acc.y += bb.y; acc.z += bb.z; acc.w += bb.w;
        acc.x = acc.x > 0.f ? acc.x : expm1f(acc.x);
        acc.y = acc.y > 0.f ? acc.y : expm1f(acc.y);
        acc.z = acc.z > 0.f ? acc.z : expm1f(acc.z);
        acc.w = acc.w > 0.f ? acc.w : expm1f(acc.w);
        ((float4*)g_h)[(size_t)node * 16 + l16] = acc;
    }
}

// ---------------- final linear 64->32 + ReLU (warp per row) ----------------
__global__ __launch_bounds__(256) void final_lin_kernel(
    const float* __restrict__ W, const float* __restrict__ b,
    float* __restrict__ out) {
    __shared__ float sw[64 * 32];
    int tid = threadIdx.x, lane = tid & 31;
    for (int i = tid; i < 64 * 32; i += 256) sw[i] = W[i];
    __syncthreads();
    int row = (blockIdx.x * blockDim.x + tid) >> 5;
    if (row >= N_NODES) return;
    const float* h = g_h + (size_t)row * 64;
    float a0 = h[lane], a1 = h[lane + 32];
    float acc = b[lane];
#pragma unroll
    for (int k = 0; k < 64; k++) {
        float av = __shfl_sync(0xffffffffu, (k < 32) ? a0 : a1, k & 31);
        acc = fmaf(av, sw[k * 32 + lane], acc);
    }
    out[(size_t)row * 32 + lane] = acc > 0.f ? acc : 0.f;
}

// ---------------- launch ----------------
extern "C" void kernel_launch(void* const* d_in, const int* in_sizes, int n_in,
                              void* d_out, int out_size) {
    const float* x      = (const float*)d_in[0];
    const void*  eidx   = d_in[1];
    const float* ew     = (const float*)d_in[2];
    const float* W1     = (const float*)d_in[3];
    const float* b1     = (const float*)d_in[4];
    const float* W_hid  = (const float*)d_in[5];
    const float* b_hid  = (const float*)d_in[6];
    const float* W_lin  = (const float*)d_in[7];
    const float* b_lin  = (const float*)d_in[8];
    float* out = (float*)d_out;

    float *h_ptr, *hw_ptr;
    void *count_ptr, *deg_ptr;
    cudaGetSymbolAddress((void**)&h_ptr, g_h);
    cudaGetSymbolAddress((void**)&hw_ptr, g_hw);
    cudaGetSymbolAddress(&count_ptr, g_count);
    cudaGetSymbolAddress(&deg_ptr, g_deg);

    // ---- graph preprocessing ----
    detect_kernel<<<1, 128>>>((const unsigned int*)eidx);
    cudaMemsetAsync(count_ptr, 0, N_NODES * sizeof(int));
    cudaMemsetAsync(deg_ptr, 0, N_NODES * sizeof(float));
    count_deg_kernel<<<N_EDGES / 256, 256>>>(eidx, ew);
    chunk_reduce_kernel<<<N_CHUNKS / 8, 256>>>();
    scan_part_kernel<<<1, N_CHUNKS>>>();
    rowptr_dinv_kernel<<<N_CHUNKS / 8, 256>>>();
    fill_kernel<<<N_EDGES / 256, 256>>>(eidx, ew);

    // ---- layer 1: 128 -> 64 ----
    gemm_n64_kernel<IN_DIM><<<N_NODES / 64, 256>>>(x, W1, hw_ptr);
    agg_elu_kernel<<<N_NODES / 8, 256>>>(hw_ptr, b1);

    // ---- hidden layers: 64 -> 64 ----
    for (int l = 0; l < N_HIDDEN; l++) {
        gemm_n64_kernel<EMB><<<N_NODES / 64, 256>>>(
            h_ptr, W_hid + (size_t)l * EMB * EMB, hw_ptr);
        agg_elu_kernel<<<N_NODES / 8, 256>>>(hw_ptr, b_hid + (size_t)l * EMB);
    }

    // ---- final linear 64 -> 32 + ReLU ----
    final_lin_kernel<<<N_NODES / 8, 256>>>(W_lin, b_lin, out);
}

// round 8
// speedup vs baseline: 1.5806x; 1.5806x over previous
#include <cuda_runtime.h>
#include <cstdint>

#define N_NODES 65536
#define N_EDGES 1048576
#define EMB 64
#define IN_DIM 128
#define OUT_DIM 32
#define N_HIDDEN 4
#define N_CHUNKS 1024   // 65536 / 64

// ---------------- scratch (static device globals; no allocation) ----------------
__device__ float g_h[N_NODES * EMB];        // layer activations
__device__ float g_hw[N_NODES * EMB];       // post-GEMM, pre-aggregation
__device__ float g_dinv[N_NODES];           // 1/sqrt(deg)
__device__ float g_deg[N_NODES];            // weighted in-degree (atomic float)
__device__ int   g_count[N_NODES];          // in-degree histogram
__device__ int   g_rowptr[N_NODES + 1];     // CSR row pointers (by dst)
__device__ int   g_work[N_NODES];           // fill cursors (copy of rowptr)
__device__ int2  g_csr[N_EDGES];            // CSR: {src, float_bits(norm_w)}
__device__ int   g_choff[N_CHUNKS];         // exclusive chunk offsets
__device__ int   g_part[N_CHUNKS];          // chunk partial sums
__device__ int   g_is64;                    // edge_index dtype flag

// ---------------- packed f32x2 helpers (Blackwell) ----------------
__device__ __forceinline__ unsigned long long pk2(float lo, float hi) {
    unsigned long long r;
    asm("mov.b64 %0, {%1, %2};" : "=l"(r) : "f"(lo), "f"(hi));
    return r;
}
__device__ __forceinline__ void fma2(unsigned long long& acc,
                                     unsigned long long a, unsigned long long b) {
    asm("fma.rn.f32x2 %0, %1, %2, %0;" : "+l"(acc) : "l"(a), "l"(b));
}
__device__ __forceinline__ float2 unpk(unsigned long long v) {
    float2 f;
    asm("mov.b64 {%0, %1}, %2;" : "=f"(f.x), "=f"(f.y) : "l"(v));
    return f;
}

// ---------------- dtype detection ----------------
__global__ void detect_kernel(const unsigned int* __restrict__ w) {
    __shared__ int s_any;
    if (threadIdx.x == 0) s_any = 0;
    __syncthreads();
    unsigned int v = w[2 * threadIdx.x + 1];
    if (v != 0) s_any = 1;
    __syncthreads();
    if (threadIdx.x == 0) g_is64 = (s_any == 0) ? 1 : 0;
}

__device__ __forceinline__ int load_idx(const void* p, int i) {
    if (g_is64) return (int)((const long long*)p)[i];
    return ((const int*)p)[i];
}

// ---------------- pass 1: count + weighted degree ----------------
__global__ void count_deg_kernel(const void* __restrict__ eidx,
                                 const float* __restrict__ ew) {
    int e = blockIdx.x * blockDim.x + threadIdx.x;
    if (e >= N_EDGES) return;
    int dst = load_idx(eidx, N_EDGES + e);
    atomicAdd(&g_count[dst], 1);
    atomicAdd(&g_deg[dst], ew[e]);
}

// ---------------- scan phase 1 ----------------
__global__ void chunk_reduce_kernel() {
    int warp = (blockIdx.x * blockDim.x + threadIdx.x) >> 5;
    int lane = threadIdx.x & 31;
    if (warp >= N_CHUNKS) return;
    int base = warp * 64;
    int v = g_count[base + lane] + g_count[base + 32 + lane];
#pragma unroll
    for (int off = 16; off > 0; off >>= 1)
        v += __shfl_down_sync(0xffffffffu, v, off);
    if (lane == 0) g_part[warp] = v;
}

// ---------------- scan phase 2 ----------------
__global__ void scan_part_kernel() {
    __shared__ int s[N_CHUNKS];
    int t = threadIdx.x;
    int orig = g_part[t];
    s[t] = orig;
    __syncthreads();
    for (int off = 1; off < N_CHUNKS; off <<= 1) {
        int v = (t >= off) ? s[t - off] : 0;
        __syncthreads();
        s[t] += v;
        __syncthreads();
    }
    g_choff[t] = s[t] - orig;  // exclusive
}

// ---------------- scan phase 3: rowptr + work + dinv ----------------
__global__ void rowptr_dinv_kernel() {
    int warp = (blockIdx.x * blockDim.x + threadIdx.x) >> 5;
    int lane = threadIdx.x & 31;
    if (warp >= N_CHUNKS) return;
    int base = warp * 64;
    int c0 = g_count[base + lane];
    int c1 = g_count[base + 32 + lane];
    int i0 = c0, i1 = c1;
#pragma unroll
    for (int off = 1; off < 32; off <<= 1) {
        int v0 = __shfl_up_sync(0xffffffffu, i0, off);
        int v1 = __shfl_up_sync(0xffffffffu, i1, off);
        if (lane >= off) { i0 += v0; i1 += v1; }
    }
    int tot0 = __shfl_sync(0xffffffffu, i0, 31);
    int off = g_choff[warp];
    int r0 = off + i0 - c0;
    int r1 = off + tot0 + i1 - c1;
    g_rowptr[base + lane] = r0;
    g_rowptr[base + 32 + lane] = r1;
    g_work[base + lane] = r0;
    g_work[base + 32 + lane] = r1;
    if (warp == N_CHUNKS - 1 && lane == 31) g_rowptr[N_NODES] = N_EDGES;
    float d, r;
    d = 1.0f + g_deg[base + lane];
    r = rsqrtf(d);
    g_dinv[base + lane] = r * (1.5f - 0.5f * d * r * r);
    d = 1.0f + g_deg[base + 32 + lane];
    r = rsqrtf(d);
    g_dinv[base + 32 + lane] = r * (1.5f - 0.5f * d * r * r);
}

// ---------------- fill CSR with normalized weights ----------------
__global__ void fill_kernel(const void* __restrict__ eidx,
                            const float* __restrict__ ew) {
    int e = blockIdx.x * blockDim.x + threadIdx.x;
    if (e >= N_EDGES) return;
    int src = load_idx(eidx, e);
    int dst = load_idx(eidx, N_EDGES + e);
    float w = ew[e] * g_dinv[src] * g_dinv[dst];
    int pos = atomicAdd(&g_work[dst], 1);
    g_csr[pos] = make_int2(src, __float_as_int(w));
}

// ---------------- tiled GEMM: C[N_NODES,N] = A[N_NODES,K] @ W[K,N] ----------------
// 256 threads: 64-row x N-col tile; thread = 4 rows x (N/16) cols; f32x2 FMAs.
// FINAL: add bias + ReLU (used for the 64->32 output projection).
template <int K, int N, bool FINAL>
__global__ __launch_bounds__(256) void gemm_tile_kernel(
    const float* __restrict__ A, const float* __restrict__ W,
    const float* __restrict__ bias, float* __restrict__ C) {
    constexpr int AP = 68;           // padded A-tile stride (16B-aligned, bank-spread)
    constexpr int CP = N / 32;       // f32x2 col-pairs per thread (2 for N=64, 1 for N=32)
    __shared__ float As[64 * AP];
    __shared__ float Ws[64 * N];
    int tid = threadIdx.x;
    int tx = tid & 15, ty = tid >> 4;
    int row0 = blockIdx.x * 64;

    unsigned long long acc[4][CP];
#pragma unroll
    for (int r = 0; r < 4; r++)
#pragma unroll
        for (int c = 0; c < CP; c++) acc[r][c] = 0ULL;

    for (int kc = 0; kc < K; kc += 64) {
        __syncthreads();
        // A tile transposed: As[k][r] = A[row0+r][kc+k]
        for (int i = tid; i < 64 * 64; i += 256) {
            int r = i >> 6, k = i & 63;
            As[k * AP + r] = A[(size_t)(row0 + r) * K + kc + k];
        }
        // W chunk: Ws[k][c] = W[kc+k][c]
        for (int i = tid; i < 64 * N; i += 256) {
            int k = i / N, c = i % N;
            Ws[k * N + c] = W[(size_t)(kc + k) * N + c];
        }
        __syncthreads();
#pragma unroll 8
        for (int k = 0; k < 64; k++) {
            float4 a = *(const float4*)&As[k * AP + ty * 4];
            unsigned long long a0 = pk2(a.x, a.x), a1 = pk2(a.y, a.y);
            unsigned long long a2 = pk2(a.z, a.z), a3 = pk2(a.w, a.w);
            if (CP == 2) {
                float4 w = *(const float4*)&Ws[k * N + tx * 4];
                unsigned long long w01 = pk2(w.x, w.y), w23 = pk2(w.z, w.w);
                fma2(acc[0][0], a0, w01); fma2(acc[0][1], a0, w23);
                fma2(acc[1][0], a1, w01); fma2(acc[1][1], a1, w23);
                fma2(acc[2][0], a2, w01); fma2(acc[2][1], a2, w23);
                fma2(acc[3][0], a3, w01); fma2(acc[3][1], a3, w23);
            } else {
                float2 w = *(const float2*)&Ws[k * N + tx * 2];
                unsigned long long w01 = pk2(w.x, w.y);
                fma2(acc[0][0], a0, w01);
                fma2(acc[1][0], a1, w01);
                fma2(acc[2][0], a2, w01);
                fma2(acc[3][0], a3, w01);
            }
        }
    }
#pragma unroll
    for (int r = 0; r < 4; r++) {
        int row = row0 + ty * 4 + r;
        if (CP == 2) {
            float2 p0 = unpk(acc[r][0]);
            float2 p1 = unpk(acc[r][1]);
            *(float4*)&C[(size_t)row * N + tx * 4] = make_float4(p0.x, p0.y, p1.x, p1.y);
        } else {
            float2 p = unpk(acc[r][0]);
            if (FINAL) {
                p.x += bias[tx * 2];
                p.y += bias[tx * 2 + 1];
                p.x = p.x > 0.f ? p.x : 0.f;
                p.y = p.y > 0.f ? p.y : 0.f;
            }
            *(float2*)&C[(size_t)row * N + tx * 2] = p;
        }
    }
}

// ---------------- aggregation + bias + ELU (R4 version — best measured) ----------------
// Warp per node. Each half-warp (16 lanes x float4) covers one full 64-float row,
// so the warp gathers 2 edges per iteration with one LDG.128 per lane.
__global__ __launch_bounds__(256) void agg_elu_kernel(
    const float* __restrict__ hw, const float* __restrict__ bias) {
    int node = (blockIdx.x * blockDim.x + threadIdx.x) >> 5;
    int lane = threadIdx.x & 31;
    if (node >= N_NODES) return;
    int half = lane >> 4;     // 0 or 1
    int l16 = lane & 15;
    const float4* hw4 = (const float4*)hw;  // row = 16 float4
    float4 acc = make_float4(0.f, 0.f, 0.f, 0.f);
    if (half == 0) {
        float di = g_dinv[node];
        float ws = di * di;
        float4 r = hw4[(size_t)node * 16 + l16];
        acc.x = ws * r.x; acc.y = ws * r.y; acc.z = ws * r.z; acc.w = ws * r.w;
    }
    int s0 = g_rowptr[node], s1 = g_rowptr[node + 1];
    for (int e = s0; e < s1; e += 2) {
        int ee = e + half;
        int2 m = (ee < s1) ? g_csr[ee] : make_int2(0, 0);  // w = 0.0f for pad
        float w = __int_as_float(m.y);
        float4 r = hw4[(size_t)m.x * 16 + l16];
        acc.x = fmaf(w, r.x, acc.x);
        acc.y = fmaf(w, r.y, acc.y);
        acc.z = fmaf(w, r.z, acc.z);
        acc.w = fmaf(w, r.w, acc.w);
    }
    // fold half 1 into half 0
    acc.x += __shfl_down_sync(0xffffffffu, acc.x, 16);
    acc.y += __shfl_down_sync(0xffffffffu, acc.y, 16);
    acc.z += __shfl_down_sync(0xffffffffu, acc.z, 16);
    acc.w += __shfl_down_sync(0xffffffffu, acc.w, 16);
    if (half == 0) {
        float4 bb = ((const float4*)bias)[l16];
        acc.x += bb.x; acc.y += bb.y; acc.z += bb.z; acc.w += bb.w;
        acc.x = acc.x > 0.f ? acc.x : expm1f(acc.x);
        acc.y = acc.y > 0.f ? acc.y : expm1f(acc.y);
        acc.z = acc.z > 0.f ? acc.z : expm1f(acc.z);
        acc.w = acc.w > 0.f ? acc.w : expm1f(acc.w);
        ((float4*)g_h)[(size_t)node * 16 + l16] = acc;
    }
}

// ---------------- launch ----------------
extern "C" void kernel_launch(void* const* d_in, const int* in_sizes, int n_in,
                              void* d_out, int out_size) {
    const float* x      = (const float*)d_in[0];
    const void*  eidx   = d_in[1];
    const float* ew     = (const float*)d_in[2];
    const float* W1     = (const float*)d_in[3];
    const float* b1     = (const float*)d_in[4];
    const float* W_hid  = (const float*)d_in[5];
    const float* b_hid  = (const float*)d_in[6];
    const float* W_lin  = (const float*)d_in[7];
    const float* b_lin  = (const float*)d_in[8];
    float* out = (float*)d_out;

    float *h_ptr, *hw_ptr;
    void *count_ptr, *deg_ptr;
    cudaGetSymbolAddress((void**)&h_ptr, g_h);
    cudaGetSymbolAddress((void**)&hw_ptr, g_hw);
    cudaGetSymbolAddress(&count_ptr, g_count);
    cudaGetSymbolAddress(&deg_ptr, g_deg);

    // ---- preprocessing + layer-1 GEMM interleaved so gemm1 is launch idx 5 (ncu target) ----
    detect_kernel<<<1, 128>>>((const unsigned int*)eidx);            // 0
    cudaMemsetAsync(count_ptr, 0, N_NODES * sizeof(int));            // 1
    cudaMemsetAsync(deg_ptr, 0, N_NODES * sizeof(float));            // 2
    count_deg_kernel<<<N_EDGES / 256, 256>>>(eidx, ew);              // 3
    chunk_reduce_kernel<<<N_CHUNKS / 8, 256>>>();                    // 4
    gemm_tile_kernel<IN_DIM, EMB, false><<<N_NODES / 64, 256>>>(     // 5 <- profiled
        x, W1, nullptr, hw_ptr);
    scan_part_kernel<<<1, N_CHUNKS>>>();                             // 6
    rowptr_dinv_kernel<<<N_CHUNKS / 8, 256>>>();                     // 7
    fill_kernel<<<N_EDGES / 256, 256>>>(eidx, ew);                   // 8

    // ---- layer 1 aggregation ----
    agg_elu_kernel<<<N_NODES / 8, 256>>>(hw_ptr, b1);                // 9

    // ---- hidden layers: 64 -> 64 ----
    for (int l = 0; l < N_HIDDEN; l++) {
        gemm_tile_kernel<EMB, EMB, false><<<N_NODES / 64, 256>>>(
            h_ptr, W_hid + (size_t)l * EMB * EMB, nullptr, hw_ptr);
        agg_elu_kernel<<<N_NODES / 8, 256>>>(hw_ptr, b_hid + (size_t)l * EMB);
    }

    // ---- final linear 64 -> 32 + bias + ReLU ----
    gemm_tile_kernel<EMB, OUT_DIM, true><<<N_NODES / 64, 256>>>(
        h_ptr, W_lin, b_lin, out);
}